// round 15
// baseline (speedup 1.0000x reference)
#include <cuda_runtime.h>
#include <cstdint>

#define S_DIM 64
#define A_DIM 32
#define M_TILE 128
#define THREADS 128

__device__ uint2 g_wfrag[32 * 32];   // prebuilt B fragments
__device__ float g_bias[128];        // b1(pad) | b2 | bopt | u

__device__ __forceinline__ uint32_t packbf(float lo, float hi) {
    uint32_t r;
    asm("cvt.rn.bf16x2.f32 %0, %1, %2;" : "=r"(r) : "f"(hi), "f"(lo));
    return r;
}
__device__ __forceinline__ float tanhfast(float x) {
    float r; asm("tanh.approx.f32 %0, %1;" : "=f"(r) : "f"(x)); return r;
}
__device__ __forceinline__ uint32_t smem_u32(const void* p) {
    uint32_t a;
    asm("{ .reg .u64 t; cvta.to.shared.u64 t, %1; cvt.u32.u64 %0, t; }"
        : "=r"(a) : "l"(p));
    return a;
}
__device__ __forceinline__ void mma16816(float c[4], const uint32_t a[4],
                                         uint32_t b0, uint32_t b1) {
    asm volatile(
        "mma.sync.aligned.m16n8k16.row.col.f32.bf16.bf16.f32 "
        "{%0,%1,%2,%3},{%4,%5,%6,%7},{%8,%9},{%0,%1,%2,%3};"
        : "+f"(c[0]), "+f"(c[1]), "+f"(c[2]), "+f"(c[3])
        : "r"(a[0]), "r"(a[1]), "r"(a[2]), "r"(a[3]), "r"(b0), "r"(b1));
}
__device__ __forceinline__ void ldm_x4(uint32_t r[4], uint32_t addr) {
    asm volatile("ldmatrix.sync.aligned.m8n8.x4.shared.b16 {%0,%1,%2,%3}, [%4];"
                 : "=r"(r[0]), "=r"(r[1]), "=r"(r[2]), "=r"(r[3]) : "r"(addr));
}

// layer-3 column permutation: lam = (ni&1)*16 + 4*t + (ni>>1)*2 + j
// -> lane t owns two contiguous float4 spans per row => 2x STG.128/slot.

// ------------- pre-kernel: build weight fragments (8 blocks) -------------
__global__ void anet_prep(const float* __restrict__ W1, const float* __restrict__ b1,
                          const float* __restrict__ W2, const float* __restrict__ b2,
                          const float* __restrict__ Wopt, const float* __restrict__ bopt,
                          const float* __restrict__ u) {
    int idx = blockIdx.x * THREADS + threadIdx.x;
    {
        int f = idx >> 5, l = idx & 31;
        int lt = l & 3, n8 = l >> 2;
        float v0, v1, v2, v3;
        if (f < 16) {
            int k0 = (f >> 2) * 16 + 2 * lt, n = (f & 3) * 8 + n8;
            bool vn = n < 30;
            v0 = vn ? W1[n * 64 + k0]     : 0.f;
            v1 = vn ? W1[n * 64 + k0 + 1] : 0.f;
            v2 = vn ? W1[n * 64 + k0 + 8] : 0.f;
            v3 = vn ? W1[n * 64 + k0 + 9] : 0.f;
        } else if (f < 24) {
            int fi = f - 16;
            int k0 = (fi >> 2) * 16 + 2 * lt, n = (fi & 3) * 8 + n8;
            v0 = (k0     < 30) ? W2[n * 30 + k0]     : 0.f;
            v1 = (k0 + 1 < 30) ? W2[n * 30 + k0 + 1] : 0.f;
            v2 = (k0 + 8 < 30) ? W2[n * 30 + k0 + 8] : 0.f;
            v3 = (k0 + 9 < 30) ? W2[n * 30 + k0 + 9] : 0.f;
        } else {
            int fi = f - 24;
            int k0 = (fi >> 2) * 16 + 2 * lt, ni = fi & 3;
            int n = ((ni & 1) << 4) + ((n8 >> 1) << 2) + ((ni >> 1) << 1) + (n8 & 1);
            v0 = Wopt[n * 32 + k0];     v1 = Wopt[n * 32 + k0 + 1];
            v2 = Wopt[n * 32 + k0 + 8]; v3 = Wopt[n * 32 + k0 + 9];
        }
        g_wfrag[idx] = make_uint2(packbf(v0, v1), packbf(v2, v3));
    }
    if (blockIdx.x == 0 && threadIdx.x < 32) {
        int tid = threadIdx.x;
        g_bias[tid]      = (tid < 30) ? b1[tid] : 0.f;
        g_bias[32 + tid] = b2[tid];
        g_bias[64 + tid] = bopt[tid];
        g_bias[96 + tid] = u[tid];
    }
}

// ---------------- main kernel ----------------
__global__ __launch_bounds__(THREADS, 5)
void anet_mma(const float* __restrict__ x, float* __restrict__ out, int batch) {
    __shared__ uint2 sBF[32 * 32];                 // 8 KB
    __shared__ float sBias[128];                   // 512 B
    __shared__ __align__(16) char sX[128 * 128];   // x bf16 swizzled, 16 KB

    const int tid  = threadIdx.x;
    const int lane = tid & 31;
    const int wid  = tid >> 5;
    const int t    = lane & 3;
    const int g    = lane >> 2;
    const uint32_t sxb = smem_u32(sX);
    const long rowBase = (long)blockIdx.x * M_TILE;
    const float4* gx = (const float4*)(x + rowBase * S_DIM);

    // ---- issue x LDGs for THIS WARP's 32 rows (512B contiguous / instr) ----
    float4 va[16];
    #pragma unroll
    for (int i = 0; i < 16; i++) {
        int fi = wid * 512 + i * 32 + lane;          // float4 idx in [128][16]
        int r = fi >> 4;
        va[i] = make_float4(0.f, 0.f, 0.f, 0.f);
        if (rowBase + r < batch) va[i] = gx[fi];
    }

    // ---- wait for prep grid (PDL); then weights are valid ----
    cudaGridDependencySynchronize();

    // ---- cooperative weight-frag + bias copy (L2-resident) ----
    {
        const uint4* gw = (const uint4*)g_wfrag;
        uint4* sw = (uint4*)sBF;
        #pragma unroll
        for (int i = 0; i < 4; i++) sw[i * THREADS + tid] = gw[i * THREADS + tid];
        sBias[tid] = g_bias[tid];
    }
    __syncthreads();            // ONLY barrier: weights visible to all warps

    const float* sb1 = sBias;
    const float* sb2 = sBias + 32;
    const float* sbo = sBias + 64;
    const float* su  = sBias + 96;

    // ---- STS x (own rows, swizzled bf16) — per-warp, no CTA barrier ----
    #pragma unroll
    for (int i = 0; i < 16; i++) {
        int fi = wid * 512 + i * 32 + lane;
        int r = fi >> 4, c8 = fi & 15;
        int c16 = c8 >> 1, half = c8 & 1;
        uint32_t off = (uint32_t)(r * 128 + ((c16 ^ (r & 7)) * 16) + half * 8);
        *(uint2*)(sX + off) = make_uint2(packbf(va[i].x, va[i].y),
                                         packbf(va[i].z, va[i].w));
    }
    __syncwarp();

    // ---- A1 fragments via ldmatrix.x4 (own rows, conflict-free) ----
    uint32_t a1f[2][4][4];
    {
        const int jt = lane >> 3;
        const int rl = (jt & 1) * 8 + (lane & 7);
        #pragma unroll
        for (int mi = 0; mi < 2; mi++) {
            int r = wid * 32 + mi * 16 + rl;
            #pragma unroll
            for (int ks = 0; ks < 4; ks++) {
                int c16 = ks * 2 + (jt >> 1);
                uint32_t addr = sxb + (uint32_t)(r * 128 + ((c16 ^ (r & 7)) * 16));
                ldm_x4(a1f[mi][ks], addr);
            }
        }
    }

    // ---- layer 1: D1[32,32] = A1[32,64] @ B1 ----
    float d1[2][4][4] = {};
    #pragma unroll
    for (int ni = 0; ni < 4; ni++) {
        uint2 bf[4];
        #pragma unroll
        for (int ks = 0; ks < 4; ks++) bf[ks] = sBF[(ks * 4 + ni) * 32 + lane];
        #pragma unroll
        for (int mi = 0; mi < 2; mi++)
            #pragma unroll
            for (int ks = 0; ks < 4; ks++)
                mma16816(d1[mi][ni], a1f[mi][ks], bf[ks].x, bf[ks].y);
    }

    // ---- epilogue 1: relu(+b1) -> A2 fragments ----
    uint32_t a2f[2][2][4];
    #pragma unroll
    for (int mi = 0; mi < 2; mi++)
        #pragma unroll
        for (int ks = 0; ks < 2; ks++)
            #pragma unroll
            for (int h = 0; h < 2; h++) {
                int ni = 2 * ks + h;
                float bl = sb1[ni * 8 + 2 * t], bh = sb1[ni * 8 + 2 * t + 1];
                a2f[mi][ks][2 * h]     = packbf(fmaxf(d1[mi][ni][0] + bl, 0.f),
                                                fmaxf(d1[mi][ni][1] + bh, 0.f));
                a2f[mi][ks][2 * h + 1] = packbf(fmaxf(d1[mi][ni][2] + bl, 0.f),
                                                fmaxf(d1[mi][ni][3] + bh, 0.f));
            }

    // ---- layer 2: D2 = H @ B2 ----
    float d2[2][4][4] = {};
    #pragma unroll
    for (int ni = 0; ni < 4; ni++) {
        uint2 bf[2];
        #pragma unroll
        for (int ks = 0; ks < 2; ks++) bf[ks] = sBF[(16 + ks * 4 + ni) * 32 + lane];
        #pragma unroll
        for (int mi = 0; mi < 2; mi++)
            #pragma unroll
            for (int ks = 0; ks < 2; ks++)
                mma16816(d2[mi][ni], a2f[mi][ks], bf[ks].x, bf[ks].y);
    }

    // ---- epilogue 2: tanh(+b2) -> A3 fragments ----
    uint32_t a3f[2][2][4];
    #pragma unroll
    for (int mi = 0; mi < 2; mi++)
        #pragma unroll
        for (int ks = 0; ks < 2; ks++)
            #pragma unroll
            for (int h = 0; h < 2; h++) {
                int ni = 2 * ks + h;
                float bl = sb2[ni * 8 + 2 * t], bh = sb2[ni * 8 + 2 * t + 1];
                a3f[mi][ks][2 * h]     = packbf(tanhfast(d2[mi][ni][0] + bl),
                                                tanhfast(d2[mi][ni][1] + bh));
                a3f[mi][ks][2 * h + 1] = packbf(tanhfast(d2[mi][ni][2] + bl),
                                                tanhfast(d2[mi][ni][3] + bh));
            }

    // ---- layer 3: D3 = T @ B3perm ----
    float d3[2][4][4] = {};
    #pragma unroll
    for (int ni = 0; ni < 4; ni++) {
        uint2 bf[2];
        #pragma unroll
        for (int ks = 0; ks < 2; ks++) bf[ks] = sBF[(24 + ks * 4 + ni) * 32 + lane];
        #pragma unroll
        for (int mi = 0; mi < 2; mi++)
            #pragma unroll
            for (int ks = 0; ks < 2; ks++)
                mma16816(d3[mi][ni], a3f[mi][ks], bf[ks].x, bf[ks].y);
    }

    // ---- projection per row; e = 2*ni+j holds logical col lam(ni,t,j) ----
    float uv[8], bov[8];
    #pragma unroll
    for (int ni = 0; ni < 4; ni++)
        #pragma unroll
        for (int j = 0; j < 2; j++) {
            int lc = ((ni & 1) << 4) + 4 * t + ((ni >> 1) << 1) + j;
            uv[2 * ni + j]  = su[lc];
            bov[2 * ni + j] = sbo[lc];
        }
    float z[4][8], y[4][8];
    bool allok = true;
    #pragma unroll
    for (int s = 0; s < 4; s++) {
        int mi = s >> 1, h = s & 1;
        float sum = 0.f;
        #pragma unroll
        for (int ni = 0; ni < 4; ni++) {
            z[s][2 * ni]     = d3[mi][ni][2 * h]     - bov[2 * ni];
            z[s][2 * ni + 1] = d3[mi][ni][2 * h + 1] - bov[2 * ni + 1];
            sum += z[s][2 * ni] + z[s][2 * ni + 1];
        }
        sum += __shfl_xor_sync(0xffffffffu, sum, 1);
        sum += __shfl_xor_sync(0xffffffffu, sum, 2);
        float lam = (sum - 90.0f) * (1.0f / 32.0f);
        bool ok = true;
        #pragma unroll
        for (int e = 0; e < 8; e++) {
            float yj = z[s][e] - lam;
            y[s][e] = yj;
            ok = ok && (yj > 0.f) && (yj < uv[e]);
        }
        int oki = ok ? 1 : 0;
        oki &= __shfl_xor_sync(0xffffffffu, oki, 1);
        oki &= __shfl_xor_sync(0xffffffffu, oki, 2);
        allok = allok && (oki != 0);
    }
    if (!__all_sync(0xffffffffu, allok)) {
        #pragma unroll 1
        for (int s = 0; s < 4; s++) {
            float lo = 1e30f, hi = -1e30f;
            #pragma unroll
            for (int e = 0; e < 8; e++) {
                lo = fminf(lo, z[s][e] - uv[e]);
                hi = fmaxf(hi, z[s][e]);
            }
            lo = fminf(lo, __shfl_xor_sync(0xffffffffu, lo, 1));
            lo = fminf(lo, __shfl_xor_sync(0xffffffffu, lo, 2));
            hi = fmaxf(hi, __shfl_xor_sync(0xffffffffu, hi, 1));
            hi = fmaxf(hi, __shfl_xor_sync(0xffffffffu, hi, 2));
            #pragma unroll 1
            for (int it = 0; it < 60; it++) {
                float mid = 0.5f * (lo + hi);
                float gs = 0.f;
                #pragma unroll
                for (int e = 0; e < 8; e++)
                    gs += fminf(fmaxf(z[s][e] - mid, 0.f), uv[e]);
                gs += __shfl_xor_sync(0xffffffffu, gs, 1);
                gs += __shfl_xor_sync(0xffffffffu, gs, 2);
                bool gt = (gs - 90.f) > 0.f;
                lo = gt ? mid : lo;
                hi = gt ? hi : mid;
            }
            float lam = 0.5f * (lo + hi);
            #pragma unroll 1
            for (int n = 0; n < 2; n++) {
                float gs = 0.f, gp = 0.f;
                #pragma unroll
                for (int e = 0; e < 8; e++) {
                    float dd = z[s][e] - lam;
                    gs += fminf(fmaxf(dd, 0.f), uv[e]);
                    gp -= ((dd > 0.f) && (dd < uv[e])) ? 1.f : 0.f;
                }
                gs += __shfl_xor_sync(0xffffffffu, gs, 1);
                gs += __shfl_xor_sync(0xffffffffu, gs, 2);
                gp += __shfl_xor_sync(0xffffffffu, gp, 1);
                gp += __shfl_xor_sync(0xffffffffu, gp, 2);
                lam -= (gs - 90.f) / ((gp == 0.f) ? -1.f : gp);
            }
            #pragma unroll
            for (int e = 0; e < 8; e++)
                y[s][e] = fminf(fmaxf(z[s][e] - lam, 0.f), uv[e]);
        }
    }

    // ---- store: 2x STG.128 per row-slot ----
    #pragma unroll
    for (int s = 0; s < 4; s++) {
        long r = rowBase + wid * 32 + (s >> 1) * 16 + (s & 1) * 8 + g;
        if (r < batch) {
            float* po = out + r * A_DIM;
            *(float4*)(po + 4 * t) =
                make_float4(y[s][0], y[s][1], y[s][4], y[s][5]);
            *(float4*)(po + 16 + 4 * t) =
                make_float4(y[s][2], y[s][3], y[s][6], y[s][7]);
        }
    }
}

extern "C" void kernel_launch(void* const* d_in, const int* in_sizes, int n_in,
                              void* d_out, int out_size) {
    const float* x    = (const float*)d_in[0];
    const float* W1   = (const float*)d_in[1];
    const float* b1   = (const float*)d_in[2];
    const float* W2   = (const float*)d_in[3];
    const float* b2   = (const float*)d_in[4];
    const float* Wopt = (const float*)d_in[5];
    const float* bopt = (const float*)d_in[6];
    const float* u    = (const float*)d_in[7];
    float* out = (float*)d_out;

    // max shared carveout -> 8 CTAs/SM resident (was ~5 at default carveout)
    cudaFuncSetAttribute(anet_mma,
                         cudaFuncAttributePreferredSharedMemoryCarveout, 100);

    int batch = in_sizes[0] / S_DIM;
    anet_prep<<<8, THREADS>>>(W1, b1, W2, b2, Wopt, bopt, u);

    // PDL launch: main starts while prep drains; preamble (x LDGs) overlaps.
    int blocks = (batch + M_TILE - 1) / M_TILE;
    cudaLaunchConfig_t cfg = {};
    cfg.gridDim  = dim3((unsigned)blocks);
    cfg.blockDim = dim3(THREADS);
    cudaLaunchAttribute attrs[1];
    attrs[0].id = cudaLaunchAttributeProgrammaticStreamSerialization;
    attrs[0].val.programmaticStreamSerializationAllowed = 1;
    cfg.attrs = attrs;
    cfg.numAttrs = 1;
    cudaLaunchKernelEx(&cfg, anet_mma, x, out, batch);
}

// round 16
// speedup vs baseline: 1.2313x; 1.2313x over previous
#include <cuda_runtime.h>
#include <cstdint>

#define S_DIM 64
#define A_DIM 32
#define M_TILE 128
#define THREADS 128

__device__ uint2 g_wfrag[32 * 32];   // prebuilt B fragments
__device__ float g_bias[128];        // b1(pad) | b2 | bopt | u

__device__ __forceinline__ uint32_t packbf(float lo, float hi) {
    uint32_t r;
    asm("cvt.rn.bf16x2.f32 %0, %1, %2;" : "=r"(r) : "f"(hi), "f"(lo));
    return r;
}
__device__ __forceinline__ float tanhfast(float x) {
    float r; asm("tanh.approx.f32 %0, %1;" : "=f"(r) : "f"(x)); return r;
}
__device__ __forceinline__ uint32_t smem_u32(const void* p) {
    uint32_t a;
    asm("{ .reg .u64 t; cvta.to.shared.u64 t, %1; cvt.u32.u64 %0, t; }"
        : "=r"(a) : "l"(p));
    return a;
}
__device__ __forceinline__ void mma16816(float c[4], const uint32_t a[4],
                                         uint32_t b0, uint32_t b1) {
    asm volatile(
        "mma.sync.aligned.m16n8k16.row.col.f32.bf16.bf16.f32 "
        "{%0,%1,%2,%3},{%4,%5,%6,%7},{%8,%9},{%0,%1,%2,%3};"
        : "+f"(c[0]), "+f"(c[1]), "+f"(c[2]), "+f"(c[3])
        : "r"(a[0]), "r"(a[1]), "r"(a[2]), "r"(a[3]), "r"(b0), "r"(b1));
}
__device__ __forceinline__ void ldm_x4(uint32_t r[4], uint32_t addr) {
    asm volatile("ldmatrix.sync.aligned.m8n8.x4.shared.b16 {%0,%1,%2,%3}, [%4];"
                 : "=r"(r[0]), "=r"(r[1]), "=r"(r[2]), "=r"(r[3]) : "r"(addr));
}

// layer-3 column permutation: lam = (ni&1)*16 + 4*t + (ni>>1)*2 + j
// -> lane t owns two contiguous float4 spans per row => 2x STG.128/slot.

// ------------- pre-kernel: build weight fragments (8 blocks) -------------
__global__ void anet_prep(const float* __restrict__ W1, const float* __restrict__ b1,
                          const float* __restrict__ W2, const float* __restrict__ b2,
                          const float* __restrict__ Wopt, const float* __restrict__ bopt,
                          const float* __restrict__ u) {
    int idx = blockIdx.x * THREADS + threadIdx.x;
    {
        int f = idx >> 5, l = idx & 31;
        int lt = l & 3, n8 = l >> 2;
        float v0, v1, v2, v3;
        if (f < 16) {
            int k0 = (f >> 2) * 16 + 2 * lt, n = (f & 3) * 8 + n8;
            bool vn = n < 30;
            v0 = vn ? W1[n * 64 + k0]     : 0.f;
            v1 = vn ? W1[n * 64 + k0 + 1] : 0.f;
            v2 = vn ? W1[n * 64 + k0 + 8] : 0.f;
            v3 = vn ? W1[n * 64 + k0 + 9] : 0.f;
        } else if (f < 24) {
            int fi = f - 16;
            int k0 = (fi >> 2) * 16 + 2 * lt, n = (fi & 3) * 8 + n8;
            v0 = (k0     < 30) ? W2[n * 30 + k0]     : 0.f;
            v1 = (k0 + 1 < 30) ? W2[n * 30 + k0 + 1] : 0.f;
            v2 = (k0 + 8 < 30) ? W2[n * 30 + k0 + 8] : 0.f;
            v3 = (k0 + 9 < 30) ? W2[n * 30 + k0 + 9] : 0.f;
        } else {
            int fi = f - 24;
            int k0 = (fi >> 2) * 16 + 2 * lt, ni = fi & 3;
            int n = ((ni & 1) << 4) + ((n8 >> 1) << 2) + ((ni >> 1) << 1) + (n8 & 1);
            v0 = Wopt[n * 32 + k0];     v1 = Wopt[n * 32 + k0 + 1];
            v2 = Wopt[n * 32 + k0 + 8]; v3 = Wopt[n * 32 + k0 + 9];
        }
        g_wfrag[idx] = make_uint2(packbf(v0, v1), packbf(v2, v3));
    }
    if (blockIdx.x == 0 && threadIdx.x < 32) {
        int tid = threadIdx.x;
        g_bias[tid]      = (tid < 30) ? b1[tid] : 0.f;
        g_bias[32 + tid] = b2[tid];
        g_bias[64 + tid] = bopt[tid];
        g_bias[96 + tid] = u[tid];
    }
}

// ---------------- main kernel ----------------
__global__ __launch_bounds__(THREADS, 5)
void anet_mma(const float* __restrict__ x, float* __restrict__ out, int batch) {
    __shared__ uint2 sBF[32 * 32];                 // 8 KB
    __shared__ float sBias[128];                   // 512 B
    __shared__ __align__(16) char sX[128 * 128];   // x bf16 swizzled, 16 KB

    const int tid  = threadIdx.x;
    const int lane = tid & 31;
    const int wid  = tid >> 5;
    const int t    = lane & 3;
    const int g    = lane >> 2;
    const uint32_t sxb = smem_u32(sX);
    const long rowBase = (long)blockIdx.x * M_TILE;
    const float4* gx = (const float4*)(x + rowBase * S_DIM);

    // ---- issue x LDGs (streaming/evict-first) for THIS WARP's 32 rows ----
    float4 va[16];
    #pragma unroll
    for (int i = 0; i < 16; i++) {
        int fi = wid * 512 + i * 32 + lane;          // float4 idx in [128][16]
        int r = fi >> 4;
        va[i] = make_float4(0.f, 0.f, 0.f, 0.f);
        if (rowBase + r < batch) va[i] = __ldcs(gx + fi);
    }

    // ---- wait for prep grid (PDL); then weights are valid ----
    cudaGridDependencySynchronize();

    // ---- cooperative weight-frag + bias copy (L2-resident) ----
    {
        const uint4* gw = (const uint4*)g_wfrag;
        uint4* sw = (uint4*)sBF;
        #pragma unroll
        for (int i = 0; i < 4; i++) sw[i * THREADS + tid] = gw[i * THREADS + tid];
        sBias[tid] = g_bias[tid];
    }
    __syncthreads();            // ONLY barrier: weights visible to all warps

    const float* sb1 = sBias;
    const float* sb2 = sBias + 32;
    const float* sbo = sBias + 64;
    const float* su  = sBias + 96;

    // ---- STS x (own rows, swizzled bf16) — per-warp, no CTA barrier ----
    #pragma unroll
    for (int i = 0; i < 16; i++) {
        int fi = wid * 512 + i * 32 + lane;
        int r = fi >> 4, c8 = fi & 15;
        int c16 = c8 >> 1, half = c8 & 1;
        uint32_t off = (uint32_t)(r * 128 + ((c16 ^ (r & 7)) * 16) + half * 8);
        *(uint2*)(sX + off) = make_uint2(packbf(va[i].x, va[i].y),
                                         packbf(va[i].z, va[i].w));
    }
    __syncwarp();

    // ---- A1 fragments via ldmatrix.x4 (own rows, conflict-free) ----
    uint32_t a1f[2][4][4];
    {
        const int jt = lane >> 3;
        const int rl = (jt & 1) * 8 + (lane & 7);
        #pragma unroll
        for (int mi = 0; mi < 2; mi++) {
            int r = wid * 32 + mi * 16 + rl;
            #pragma unroll
            for (int ks = 0; ks < 4; ks++) {
                int c16 = ks * 2 + (jt >> 1);
                uint32_t addr = sxb + (uint32_t)(r * 128 + ((c16 ^ (r & 7)) * 16));
                ldm_x4(a1f[mi][ks], addr);
            }
        }
    }

    // ---- layer 1: D1[32,32] = A1[32,64] @ B1 ----
    float d1[2][4][4] = {};
    #pragma unroll
    for (int ni = 0; ni < 4; ni++) {
        uint2 bf[4];
        #pragma unroll
        for (int ks = 0; ks < 4; ks++) bf[ks] = sBF[(ks * 4 + ni) * 32 + lane];
        #pragma unroll
        for (int mi = 0; mi < 2; mi++)
            #pragma unroll
            for (int ks = 0; ks < 4; ks++)
                mma16816(d1[mi][ni], a1f[mi][ks], bf[ks].x, bf[ks].y);
    }

    // ---- epilogue 1: relu(+b1) -> A2 fragments ----
    uint32_t a2f[2][2][4];
    #pragma unroll
    for (int mi = 0; mi < 2; mi++)
        #pragma unroll
        for (int ks = 0; ks < 2; ks++)
            #pragma unroll
            for (int h = 0; h < 2; h++) {
                int ni = 2 * ks + h;
                float bl = sb1[ni * 8 + 2 * t], bh = sb1[ni * 8 + 2 * t + 1];
                a2f[mi][ks][2 * h]     = packbf(fmaxf(d1[mi][ni][0] + bl, 0.f),
                                                fmaxf(d1[mi][ni][1] + bh, 0.f));
                a2f[mi][ks][2 * h + 1] = packbf(fmaxf(d1[mi][ni][2] + bl, 0.f),
                                                fmaxf(d1[mi][ni][3] + bh, 0.f));
            }

    // ---- layer 2: D2 = H @ B2 ----
    float d2[2][4][4] = {};
    #pragma unroll
    for (int ni = 0; ni < 4; ni++) {
        uint2 bf[2];
        #pragma unroll
        for (int ks = 0; ks < 2; ks++) bf[ks] = sBF[(16 + ks * 4 + ni) * 32 + lane];
        #pragma unroll
        for (int mi = 0; mi < 2; mi++)
            #pragma unroll
            for (int ks = 0; ks < 2; ks++)
                mma16816(d2[mi][ni], a2f[mi][ks], bf[ks].x, bf[ks].y);
    }

    // ---- epilogue 2: tanh(+b2) -> A3 fragments ----
    uint32_t a3f[2][2][4];
    #pragma unroll
    for (int mi = 0; mi < 2; mi++)
        #pragma unroll
        for (int ks = 0; ks < 2; ks++)
            #pragma unroll
            for (int h = 0; h < 2; h++) {
                int ni = 2 * ks + h;
                float bl = sb2[ni * 8 + 2 * t], bh = sb2[ni * 8 + 2 * t + 1];
                a3f[mi][ks][2 * h]     = packbf(tanhfast(d2[mi][ni][0] + bl),
                                                tanhfast(d2[mi][ni][1] + bh));
                a3f[mi][ks][2 * h + 1] = packbf(tanhfast(d2[mi][ni][2] + bl),
                                                tanhfast(d2[mi][ni][3] + bh));
            }

    // ---- layer 3: D3 = T @ B3perm ----
    float d3[2][4][4] = {};
    #pragma unroll
    for (int ni = 0; ni < 4; ni++) {
        uint2 bf[2];
        #pragma unroll
        for (int ks = 0; ks < 2; ks++) bf[ks] = sBF[(24 + ks * 4 + ni) * 32 + lane];
        #pragma unroll
        for (int mi = 0; mi < 2; mi++)
            #pragma unroll
            for (int ks = 0; ks < 2; ks++)
                mma16816(d3[mi][ni], a3f[mi][ks], bf[ks].x, bf[ks].y);
    }

    // ---- projection per row; e = 2*ni+j holds logical col lam(ni,t,j) ----
    float uv[8], bov[8];
    #pragma unroll
    for (int ni = 0; ni < 4; ni++)
        #pragma unroll
        for (int j = 0; j < 2; j++) {
            int lc = ((ni & 1) << 4) + 4 * t + ((ni >> 1) << 1) + j;
            uv[2 * ni + j]  = su[lc];
            bov[2 * ni + j] = sbo[lc];
        }
    float z[4][8], y[4][8];
    bool allok = true;
    #pragma unroll
    for (int s = 0; s < 4; s++) {
        int mi = s >> 1, h = s & 1;
        float sum = 0.f;
        #pragma unroll
        for (int ni = 0; ni < 4; ni++) {
            z[s][2 * ni]     = d3[mi][ni][2 * h]     - bov[2 * ni];
            z[s][2 * ni + 1] = d3[mi][ni][2 * h + 1] - bov[2 * ni + 1];
            sum += z[s][2 * ni] + z[s][2 * ni + 1];
        }
        sum += __shfl_xor_sync(0xffffffffu, sum, 1);
        sum += __shfl_xor_sync(0xffffffffu, sum, 2);
        float lam = (sum - 90.0f) * (1.0f / 32.0f);
        bool ok = true;
        #pragma unroll
        for (int e = 0; e < 8; e++) {
            float yj = z[s][e] - lam;
            y[s][e] = yj;
            ok = ok && (yj > 0.f) && (yj < uv[e]);
        }
        int oki = ok ? 1 : 0;
        oki &= __shfl_xor_sync(0xffffffffu, oki, 1);
        oki &= __shfl_xor_sync(0xffffffffu, oki, 2);
        allok = allok && (oki != 0);
    }
    if (!__all_sync(0xffffffffu, allok)) {
        #pragma unroll 1
        for (int s = 0; s < 4; s++) {
            float lo = 1e30f, hi = -1e30f;
            #pragma unroll
            for (int e = 0; e < 8; e++) {
                lo = fminf(lo, z[s][e] - uv[e]);
                hi = fmaxf(hi, z[s][e]);
            }
            lo = fminf(lo, __shfl_xor_sync(0xffffffffu, lo, 1));
            lo = fminf(lo, __shfl_xor_sync(0xffffffffu, lo, 2));
            hi = fmaxf(hi, __shfl_xor_sync(0xffffffffu, hi, 1));
            hi = fmaxf(hi, __shfl_xor_sync(0xffffffffu, hi, 2));
            #pragma unroll 1
            for (int it = 0; it < 60; it++) {
                float mid = 0.5f * (lo + hi);
                float gs = 0.f;
                #pragma unroll
                for (int e = 0; e < 8; e++)
                    gs += fminf(fmaxf(z[s][e] - mid, 0.f), uv[e]);
                gs += __shfl_xor_sync(0xffffffffu, gs, 1);
                gs += __shfl_xor_sync(0xffffffffu, gs, 2);
                bool gt = (gs - 90.f) > 0.f;
                lo = gt ? mid : lo;
                hi = gt ? hi : mid;
            }
            float lam = 0.5f * (lo + hi);
            #pragma unroll 1
            for (int n = 0; n < 2; n++) {
                float gs = 0.f, gp = 0.f;
                #pragma unroll
                for (int e = 0; e < 8; e++) {
                    float dd = z[s][e] - lam;
                    gs += fminf(fmaxf(dd, 0.f), uv[e]);
                    gp -= ((dd > 0.f) && (dd < uv[e])) ? 1.f : 0.f;
                }
                gs += __shfl_xor_sync(0xffffffffu, gs, 1);
                gs += __shfl_xor_sync(0xffffffffu, gs, 2);
                gp += __shfl_xor_sync(0xffffffffu, gp, 1);
                gp += __shfl_xor_sync(0xffffffffu, gp, 2);
                lam -= (gs - 90.f) / ((gp == 0.f) ? -1.f : gp);
            }
            #pragma unroll
            for (int e = 0; e < 8; e++)
                y[s][e] = fminf(fmaxf(z[s][e] - lam, 0.f), uv[e]);
        }
    }

    // ---- store: 2x STG.128 per row-slot, streaming (evict-first) ----
    #pragma unroll
    for (int s = 0; s < 4; s++) {
        long r = rowBase + wid * 32 + (s >> 1) * 16 + (s & 1) * 8 + g;
        if (r < batch) {
            float* po = out + r * A_DIM;
            __stcs((float4*)(po + 4 * t),
                   make_float4(y[s][0], y[s][1], y[s][4], y[s][5]));
            __stcs((float4*)(po + 16 + 4 * t),
                   make_float4(y[s][2], y[s][3], y[s][6], y[s][7]));
        }
    }
}

extern "C" void kernel_launch(void* const* d_in, const int* in_sizes, int n_in,
                              void* d_out, int out_size) {
    const float* x    = (const float*)d_in[0];
    const float* W1   = (const float*)d_in[1];
    const float* b1   = (const float*)d_in[2];
    const float* W2   = (const float*)d_in[3];
    const float* b2   = (const float*)d_in[4];
    const float* Wopt = (const float*)d_in[5];
    const float* bopt = (const float*)d_in[6];
    const float* u    = (const float*)d_in[7];
    float* out = (float*)d_out;

    int batch = in_sizes[0] / S_DIM;
    anet_prep<<<8, THREADS>>>(W1, b1, W2, b2, Wopt, bopt, u);

    // PDL launch: main starts while prep drains; preamble (x LDGs) overlaps.
    int blocks = (batch + M_TILE - 1) / M_TILE;
    cudaLaunchConfig_t cfg = {};
    cfg.gridDim  = dim3((unsigned)blocks);
    cfg.blockDim = dim3(THREADS);
    cudaLaunchAttribute attrs[1];
    attrs[0].id = cudaLaunchAttributeProgrammaticStreamSerialization;
    attrs[0].val.programmaticStreamSerializationAllowed = 1;
    cfg.attrs = attrs;
    cfg.numAttrs = 1;
    cudaLaunchKernelEx(&cfg, anet_mma, x, out, batch);
}